// round 6
// baseline (speedup 1.0000x reference)
#include <cuda_runtime.h>
#include <cuda_bf16.h>
#include <cstdint>

// Resample2d (FlowNet2 bilinear warp), fixed shapes:
//   input1 [B=4, C=64, H=384, W=512] fp32
//   input2 [B=4, 2,    H=384, W=512] fp32  (dx, dy)
//   out    [B=4, C=64, H=384, W=512] fp32
//
// R6: 4 pixels (same row, consecutive w) per thread.
//   - gathers stay scalar LDG.32 (measured cost: ~1 L1 unit each; LDG.64
//     gathers cost 2 -- R5 regression)
//   - store becomes one STG.128 per channel (4 outputs)
//   - flow read as float4 (2 LDG.128 per pixel-quad, amortized over 64 ch)
//   - weights/offsets computed once per pixel-quad, reused across channels
// Discriminates L1 slot-model (predict ~95-100us) vs byte-model (~114us).

#define RS_B 4
#define RS_C 64
#define RS_H 384
#define RS_W 512
#define RS_HW (RS_H * RS_W)
#define RS_CHW (RS_C * RS_HW)

__global__ __launch_bounds__(256, 4) void resample2d_q4_kernel(
    const float* __restrict__ in1,   // [B,C,H,W]
    const float* __restrict__ flow,  // [B,2,H,W]
    float* __restrict__ out)         // [B,C,H,W]
{
    const int q = blockIdx.x * 256 + threadIdx.x;   // pixel-quad index
    const int b = blockIdx.y;
    const int p0 = q * 4;                            // first pixel (h*W+w)
    if (p0 >= RS_HW) return;

    const int w0 = p0 & (RS_W - 1);
    const int h  = p0 >> 9;                          // W = 512 = 2^9; same row for all 4

    const float* flowb = flow + b * 2 * RS_HW;
    const float4 dx4 = __ldg((const float4*)(flowb + p0));
    const float4 dy4 = __ldg((const float4*)(flowb + RS_HW + p0));

    // per-pixel params
    float wTL[4], wTR[4], wBL[4], wBR[4];
    int aT_L[4], aT_R[4], dB[4];     // top-row offsets for L/R taps; +dB = bottom row

    const float dxs[4] = {dx4.x, dx4.y, dx4.z, dx4.w};
    const float dys[4] = {dy4.x, dy4.y, dy4.z, dy4.w};

#pragma unroll
    for (int i = 0; i < 4; ++i) {
        const float xf = (float)(w0 + i) + dxs[i];
        const float yf = (float)h + dys[i];
        const float x0 = floorf(xf);
        const float y0 = floorf(yf);
        const float alpha = xf - x0;
        const float beta  = yf - y0;

        const int x0i = (int)x0;
        const int y0i = (int)y0;
        const int xL = min(max(x0i,     0), RS_W - 1);
        const int xR = min(max(x0i + 1, 0), RS_W - 1);
        const int yT = min(max(y0i,     0), RS_H - 1);
        const int yB = min(max(y0i + 1, 0), RS_H - 1);

        wTR[i] = alpha * (1.0f - beta);
        wBL[i] = (1.0f - alpha) * beta;
        wBR[i] = alpha * beta;
        wTL[i] = 1.0f - wTR[i] - wBL[i] - wBR[i];

        aT_L[i] = yT * RS_W + xL;
        aT_R[i] = yT * RS_W + xR;
        dB[i]   = (yB - yT) * RS_W;          // 0 or 512
    }

    const float* base = in1 + b * RS_CHW;
    float* outp = out + b * RS_CHW + p0;

#pragma unroll 2
    for (int c = 0; c < RS_C; ++c) {
        const float* p = base + c * RS_HW;
        float4 o;
        float r[4];
#pragma unroll
        for (int i = 0; i < 4; ++i) {
            const float vTL = __ldg(p + aT_L[i]);
            const float vTR = __ldg(p + aT_R[i]);
            const float vBL = __ldg(p + aT_L[i] + dB[i]);
            const float vBR = __ldg(p + aT_R[i] + dB[i]);
            r[i] = fmaf(wTL[i], vTL,
                   fmaf(wTR[i], vTR,
                   fmaf(wBL[i], vBL,
                        wBR[i] * vBR)));
        }
        o.x = r[0]; o.y = r[1]; o.z = r[2]; o.w = r[3];
        *(float4*)(outp + c * RS_HW) = o;
    }
}

extern "C" void kernel_launch(void* const* d_in, const int* in_sizes, int n_in,
                              void* d_out, int out_size)
{
    const float* in1  = (const float*)d_in[0];
    const float* flow = (const float*)d_in[1];
    float* out = (float*)d_out;

    dim3 grid(RS_HW / 4 / 256, RS_B);   // 192 x 4 = 768 blocks
    resample2d_q4_kernel<<<grid, 256>>>(in1, flow, out);
}

// round 8
// speedup vs baseline: 1.8649x; 1.8649x over previous
#include <cuda_runtime.h>
#include <cuda_bf16.h>
#include <cstdint>

// Resample2d (FlowNet2 bilinear warp), fixed shapes:
//   input1 [B=4, C=64, H=384, W=512] fp32
//   input2 [B=4, 2,    H=384, W=512] fp32  (dx, dy)
//   out    [B=4, C=64, H=384, W=512] fp32
//
// R8 = re-bench of R7 (container failure was infra, not a verdict).
// R1 structure (one pixel/thread, warp = 32 consecutive columns -- the only
// shape that keeps scattered-gather cost at ~1 L1 cycle/instr), tuned for
// occupancy: launch_bounds(256,8) forces <=32 regs -> 8 CTAs/SM, unroll 2
// to stay within budget, streaming store (__stcs) + streaming flow load
// (__ldcs) to keep L2 for input1 gather-overlap reuse.

#define RS_B 4
#define RS_C 64
#define RS_H 384
#define RS_W 512
#define RS_HW (RS_H * RS_W)
#define RS_CHW (RS_C * RS_HW)

__global__ __launch_bounds__(256, 8) void resample2d_kernel(
    const float* __restrict__ in1,   // [B,C,H,W]
    const float* __restrict__ flow,  // [B,2,H,W]
    float* __restrict__ out)         // [B,C,H,W]
{
    const int t = blockIdx.x * 256 + threadIdx.x;   // pixel index h*W+w
    const int b = blockIdx.y;
    if (t >= RS_HW) return;

    const int w = t & (RS_W - 1);
    const int h = t >> 9;                            // W = 512 = 2^9

    const float* flowb = flow + b * 2 * RS_HW;
    const float dx = __ldcs(flowb + t);
    const float dy = __ldcs(flowb + RS_HW + t);

    const float xf = (float)w + dx;
    const float yf = (float)h + dy;
    const float x0 = floorf(xf);
    const float y0 = floorf(yf);
    const float alpha = xf - x0;
    const float beta  = yf - y0;

    const int x0i = (int)x0;
    const int y0i = (int)y0;
    const int xL = min(max(x0i,     0), RS_W - 1);
    const int xR = min(max(x0i + 1, 0), RS_W - 1);
    const int yT = min(max(y0i,     0), RS_H - 1);
    const int yB = min(max(y0i + 1, 0), RS_H - 1);

    const float wTR = alpha * (1.0f - beta);
    const float wBL = (1.0f - alpha) * beta;
    const float wBR = alpha * beta;
    const float wTL = 1.0f - wTR - wBL - wBR;

    // Four gather base addresses for channel 0; channel step = HW floats.
    const float* base = in1 + b * RS_CHW;
    const float* pTL = base + yT * RS_W + xL;
    const float* pTR = base + yT * RS_W + xR;
    const float* pBL = base + yB * RS_W + xL;
    const float* pBR = base + yB * RS_W + xR;
    float* outp = out + b * RS_CHW + t;

#pragma unroll 2
    for (int c = 0; c < RS_C; ++c) {
        const int o = c * RS_HW;
        const float vTL = __ldg(pTL + o);
        const float vTR = __ldg(pTR + o);
        const float vBL = __ldg(pBL + o);
        const float vBR = __ldg(pBR + o);
        __stcs(outp + o,
               fmaf(wTL, vTL,
               fmaf(wTR, vTR,
               fmaf(wBL, vBL,
                    wBR * vBR))));
    }
}

extern "C" void kernel_launch(void* const* d_in, const int* in_sizes, int n_in,
                              void* d_out, int out_size)
{
    const float* in1  = (const float*)d_in[0];
    const float* flow = (const float*)d_in[1];
    float* out = (float*)d_out;

    dim3 grid(RS_HW / 256, RS_B);   // 768 x 4 = 3072 blocks
    resample2d_kernel<<<grid, 256>>>(in1, flow, out);
}